// round 11
// baseline (speedup 1.0000x reference)
#include <cuda_runtime.h>
#include <math.h>

// ---------------------------------------------------------------------------
// FCOS post-processing, 2 kernels.
//   decode (grid-wide): scores+classes; pushes candidates with score >= T0
//                       to per-batch lists (rare predicated atomic).
//   nms (block/batch):  per-class warp NMS over ~800 candidates + top-100 out.
// Exactness: {score>=T0} contains the global top-|set|; suppression is
// intra-class and flows down-rank, so if >=100 of the T0-candidates survive,
// they are exactly the reference's first 100 picks (verified at runtime;
// exact full-array fallback otherwise — statistically unreachable).
// ---------------------------------------------------------------------------

#define BATCH   16
#define NCLS    80
#define NTOT    17064          // 12800 + 3200 + 800 + 208 + 56
#define NGROUP  (NTOT / 4)     // 4266
#define POSTK   100
#define CAP     4096
#define CLSCAP  128
#define NTN     1024
#define T0      0.88f

__device__ float         g_score[BATCH * NTOT];
__device__ unsigned char g_cls  [BATCH * NTOT];
__device__ int           g_cnt  [BATCH];          // zero-initialized at load
__device__ float         g_cand_s[BATCH * CAP];
__device__ int           g_cand_i[BATCH * CAP];   // anchor | (cls<<16)

struct LevelPtrs {
    const float* cls[5];
    const float* box[5];
    const float* ctr[5];
};

__constant__ int   c_off[6]    = {0, 12800, 16000, 16800, 17008, 17064};
__constant__ int   c_W[5]      = {128, 64, 32, 16, 8};
__constant__ float c_stride[5] = {8.f, 16.f, 32.f, 64.f, 128.f};

__device__ __forceinline__ float sigmoidf_(float x) {
    return 1.0f / (1.0f + expf(-x));
}
__device__ __forceinline__ float iou_(const float4 a, const float4 b) {
    float ix1 = fmaxf(a.x, b.x), iy1 = fmaxf(a.y, b.y);
    float ix2 = fminf(a.z, b.z), iy2 = fminf(a.w, b.w);
    float inter = fmaxf(ix2 - ix1, 0.f) * fmaxf(iy2 - iy1, 0.f);
    float aa = (a.z - a.x) * (a.w - a.y);
    float ab = (b.z - b.x) * (b.w - b.y);
    return inter / (aa + ab - inter + 1e-9f);
}
__device__ __forceinline__ float4 decode_box(const LevelPtrs& p, int b, int a) {
    int lvl = (a >= 12800) + (a >= 16000) + (a >= 16800) + (a >= 17008);
    int   hw     = a - c_off[lvl];
    int   HW     = c_off[lvl + 1] - c_off[lvl];
    int   W      = c_W[lvl];
    float stride = c_stride[lvl];
    const float* bp = p.box[lvl] + (size_t)b * 4 * HW + hw;
    float l  = bp[0]      * stride;
    float t  = bp[HW]     * stride;
    float r  = bp[2 * HW] * stride;
    float d  = bp[3 * HW] * stride;
    float px = (hw % W) * stride + 0.5f * stride;
    float py = (hw / W) * stride + 0.5f * stride;
    return make_float4(fminf(fmaxf(px - l, 0.f), 1023.f),
                       fminf(fmaxf(py - t, 0.f), 799.f),
                       fminf(fmaxf(px + r, 0.f), 1023.f),
                       fminf(fmaxf(py + d, 0.f), 799.f));
}

// ---------------------------------------------------------------------------
// Decode: scores + classes; push candidates >= T0. One thread per 4 anchors.
// ---------------------------------------------------------------------------
__global__ void decode_kernel(LevelPtrs p) {
    int g = blockIdx.x * blockDim.x + threadIdx.x;
    int b = blockIdx.y;
    if (g >= NGROUP) return;
    int a0 = g * 4;

    int lvl = (a0 >= 12800) + (a0 >= 16000) + (a0 >= 16800) + (a0 >= 17008);
    int hw0 = a0 - c_off[lvl];
    int HW  = c_off[lvl + 1] - c_off[lvl];
    int HW4 = HW >> 2;

    const float4* __restrict__ cp = reinterpret_cast<const float4*>(
        p.cls[lvl] + (size_t)b * NCLS * HW + hw0);
    float4 best = cp[0];
    int4   bi   = make_int4(0, 0, 0, 0);
#pragma unroll 8
    for (int c = 1; c < NCLS; c++) {
        float4 v = cp[(size_t)c * HW4];
        if (v.x > best.x) { best.x = v.x; bi.x = c; }
        if (v.y > best.y) { best.y = v.y; bi.y = c; }
        if (v.z > best.z) { best.z = v.z; bi.z = c; }
        if (v.w > best.w) { best.w = v.w; bi.w = c; }
    }

    float4 ct = *reinterpret_cast<const float4*>(p.ctr[lvl] + (size_t)b * HW + hw0);

    float4 s4;
    s4.x = sqrtf(sigmoidf_(best.x) * sigmoidf_(ct.x));
    s4.y = sqrtf(sigmoidf_(best.y) * sigmoidf_(ct.y));
    s4.z = sqrtf(sigmoidf_(best.z) * sigmoidf_(ct.z));
    s4.w = sqrtf(sigmoidf_(best.w) * sigmoidf_(ct.w));

    int gi = b * NTOT + a0;
    reinterpret_cast<float4*>(g_score)[gi >> 2] = s4;
    *reinterpret_cast<uchar4*>(&g_cls[gi]) =
        make_uchar4((unsigned char)bi.x, (unsigned char)bi.y,
                    (unsigned char)bi.z, (unsigned char)bi.w);

    float sA[4] = {s4.x, s4.y, s4.z, s4.w};
    int   cA[4] = {bi.x, bi.y, bi.z, bi.w};
#pragma unroll
    for (int j = 0; j < 4; j++) {
        if (sA[j] >= T0) {
            int pos = atomicAdd(&g_cnt[b], 1);
            if (pos < CAP) {
                g_cand_s[b * CAP + pos] = sA[j];
                g_cand_i[b * CAP + pos] = (a0 + j) | (cA[j] << 16);
            }
        }
    }
}

// ---------------------------------------------------------------------------
// NMS: one block per batch over the ~800 candidates.
// ---------------------------------------------------------------------------
extern __shared__ char smemn[];

__global__ void __launch_bounds__(NTN, 1) nms_kernel(LevelPtrs p,
                                                     float* __restrict__ out) {
    float4*         so_box   = (float4*)smemn;                            // 64K
    float*          st_s     = (float*)(smemn + CAP * 16);                // 16K
    int*            st_i     = (int*)((char*)st_s + CAP * 4);             // 16K
    unsigned char*  st_c     = (unsigned char*)((char*)st_i + CAP * 4);   // 4K
    unsigned char*  keep     = st_c + CAP;                                // 4K
    unsigned short* cls_list = (unsigned short*)(keep + CAP);             // 20K
    unsigned short* sv       = cls_list + NCLS * CLSCAP;                  // 8K

    __shared__ int    s_ccnt[NCLS];
    __shared__ int    s_ovf, s_nsurv;
    __shared__ float  s_bv[32];
    __shared__ int    s_bi[32];
    __shared__ float4 s_pbox;
    __shared__ int    s_pcls;
    __shared__ float  s_pval;

    const int b    = blockIdx.x;
    const int tid  = threadIdx.x;
    const int warp = tid >> 5;
    const int lane = tid & 31;

    const int total = g_cnt[b];
    const int C     = min(total, CAP);
    __syncthreads();
    if (tid == 0) { g_cnt[b] = 0; s_ovf = 0; s_nsurv = 0; }  // reset for next replay
    __syncthreads();

    // ---- load candidates, compute boxes -----------------------------------
    for (int i = tid; i < C; i += NTN) {
        float s  = g_cand_s[b * CAP + i];
        int   pk = g_cand_i[b * CAP + i];
        int   a  = pk & 0xFFFF;
        st_s[i] = s;
        st_i[i] = a;
        st_c[i] = (unsigned char)(pk >> 16);
        so_box[i] = decode_box(p, b, a);
        keep[i] = 1;
    }
    __syncthreads();

    // ---- per-class compaction (warp ballot) -------------------------------
    for (int c = warp; c < NCLS; c += 32) {
        int m = 0;
        for (int base = 0; base < C; base += 32) {
            int  i  = base + lane;
            bool pr = (i < C) && (st_c[i] == (unsigned char)c);
            unsigned mask = __ballot_sync(0xffffffffu, pr);
            if (pr) {
                int pos = m + __popc(mask & ((1u << lane) - 1));
                if (pos < CLSCAP)
                    cls_list[c * CLSCAP + pos] = (unsigned short)i;
            }
            m += __popc(mask);
        }
        if (lane == 0) {
            s_ccnt[c] = m;
            if (m > CLSCAP) atomicExch(&s_ovf, 1);
        }
    }
    __syncthreads();

    if (!s_ovf) {
        // ---- per-class: rank sort (score desc, idx asc) then greedy -------
        for (int c = warp; c < NCLS; c += 32) {
            int m = s_ccnt[c];
            unsigned short* L = cls_list + c * CLSCAP;
            int slotA[4], rA[4], cnt = 0;
            for (int i = lane; i < m; i += 32) {
                int   sl = L[i];
                float si = st_s[sl];
                int   ai = st_i[sl];
                int   r  = 0;
                for (int j = 0; j < m; j++) {
                    int   s2 = L[j];
                    float sj = st_s[s2];
                    r += (sj > si) || (sj == si && st_i[s2] < ai);
                }
                slotA[cnt] = sl; rA[cnt] = r; cnt++;
            }
            __syncwarp();
            for (int q = 0; q < cnt; q++) L[rA[q]] = (unsigned short)slotA[q];
            __syncwarp();
            for (int r = 0; r < m; r++) {
                int ir = L[r];
                if (keep[ir]) {
                    float4 pb = so_box[ir];
                    for (int j = r + 1 + lane; j < m; j += 32) {
                        int ij = L[j];
                        if (keep[ij] && iou_(pb, so_box[ij]) > 0.6f)
                            keep[ij] = 0;
                    }
                }
                __syncwarp();
            }
        }
    }
    __syncthreads();

    // ---- survivor collection ----------------------------------------------
    if (!s_ovf) {
        for (int i = tid; i < C; i += NTN) {
            if (keep[i]) {
                int pos = atomicAdd(&s_nsurv, 1);
                sv[pos] = (unsigned short)i;
            }
        }
    }
    __syncthreads();
    int S = s_nsurv;

    bool exact = !s_ovf && (total <= CAP) && (S >= POSTK);
    if (exact) {
        // ---- rank survivors, write top-100 --------------------------------
        for (int i = tid; i < S; i += NTN) {
            int   sl = sv[i];
            float si = st_s[sl];
            int   ai = st_i[sl];
            int   r  = 0;
            for (int j = 0; j < S; j++) {
                int   s2 = sv[j];
                float sj = st_s[s2];
                r += (sj > si) || (sj == si && st_i[s2] < ai);
            }
            if (r < POSTK) {
                float4 bb  = so_box[sl];
                float* det = out + ((size_t)b * POSTK + r) * 5;
                det[0] = bb.x; det[1] = bb.y; det[2] = bb.z; det[3] = bb.w;
                det[4] = si;
                out[(size_t)BATCH * POSTK * 5 + b * POSTK + r] = (float)st_c[sl];
            }
        }
        return;
    }

    // ---- fallback: exact block-serial greedy over all anchors -------------
    // (statistically unreachable; g_score is replay-rewritten scratch)
    {
        float* gsm = g_score + b * NTOT;
        int written = 0;
        for (int k = 0; k < POSTK; k++) {
            float bv = -1e30f; int bix = 0x7fffffff;
            for (int i = tid; i < NTOT; i += NTN) {
                float s = gsm[i];
                if (s > bv || (s == bv && i < bix)) { bv = s; bix = i; }
            }
#pragma unroll
            for (int off = 16; off; off >>= 1) {
                float ov = __shfl_down_sync(0xffffffffu, bv, off);
                int   oi = __shfl_down_sync(0xffffffffu, bix, off);
                if (ov > bv || (ov == bv && oi < bix)) { bv = ov; bix = oi; }
            }
            if (lane == 0) { s_bv[warp] = bv; s_bi[warp] = bix; }
            __syncthreads();
            if (tid == 0) {
                float fv = -1e30f; int fi = 0x7fffffff;
                for (int w2 = 0; w2 < 32; w2++) {
                    float cv = s_bv[w2]; int ci = s_bi[w2];
                    if (cv > fv || (cv == fv && ci < fi)) { fv = cv; fi = ci; }
                }
                s_pval = fv;
                if (fv > -1e29f) {
                    float4 pb = decode_box(p, b, fi);
                    s_pbox = pb;
                    s_pcls = g_cls[b * NTOT + fi];
                    float* det = out + ((size_t)b * POSTK + k) * 5;
                    det[0] = pb.x; det[1] = pb.y; det[2] = pb.z; det[3] = pb.w;
                    det[4] = fv;
                    out[(size_t)BATCH * POSTK * 5 + b * POSTK + k] =
                        (float)s_pcls;
                    gsm[fi] = -1e30f;
                }
            }
            __syncthreads();
            if (s_pval <= -1e29f) break;
            written++;
            float4 pb = s_pbox;
            int    pc = s_pcls;
            for (int i = tid; i < NTOT; i += NTN) {
                float s = gsm[i];
                if (s > -1e29f && g_cls[b * NTOT + i] == pc) {
                    if (iou_(pb, decode_box(p, b, i)) > 0.6f) gsm[i] = -1e30f;
                }
            }
            __syncthreads();
        }
        for (int k = written + tid; k < POSTK; k += NTN) {
            float* det = out + ((size_t)b * POSTK + k) * 5;
            det[0] = 0.f; det[1] = 0.f; det[2] = 0.f; det[3] = 0.f; det[4] = -1.f;
            out[(size_t)BATCH * POSTK * 5 + b * POSTK + k] = -1.f;
        }
    }
}

// ---------------------------------------------------------------------------
extern "C" void kernel_launch(void* const* d_in, const int* in_sizes, int n_in,
                              void* d_out, int out_size) {
    (void)n_in; (void)out_size;

    LevelPtrs p;
    if (in_sizes[1] == 819200) {
        for (int i = 0; i < 5; i++) {          // interleaved (cls,box,ctr)/level
            p.cls[i] = (const float*)d_in[3 * i + 0];
            p.box[i] = (const float*)d_in[3 * i + 1];
            p.ctr[i] = (const float*)d_in[3 * i + 2];
        }
    } else {
        for (int i = 0; i < 5; i++) {          // planar cls x5, box x5, ctr x5
            p.cls[i] = (const float*)d_in[i];
            p.box[i] = (const float*)d_in[5 + i];
            p.ctr[i] = (const float*)d_in[10 + i];
        }
    }

    const int smem_bytes = CAP * 16 + CAP * 4 + CAP * 4 + CAP + CAP
                         + NCLS * CLSCAP * 2 + CAP * 2;   // 135,168 B
    cudaFuncSetAttribute(nms_kernel,
                         cudaFuncAttributeMaxDynamicSharedMemorySize, smem_bytes);

    dim3 dgrid((NGROUP + 255) / 256, BATCH);
    decode_kernel<<<dgrid, 256>>>(p);

    nms_kernel<<<BATCH, NTN, smem_bytes>>>(p, (float*)d_out);
}

// round 12
// speedup vs baseline: 2.4827x; 2.4827x over previous
#include <cuda_runtime.h>
#include <math.h>

// ---------------------------------------------------------------------------
// FCOS post-processing, 2 kernels.
//   decode (grid-wide): scores+classes; pushes candidates with score >= T0.
//   nms (block/batch):  histogram-prune to top-K prefix (K~220) -> global rank
//                       sort -> per-class warp greedy -> ballot-scan ranks.
// Exactness: bin-thresholded candidate sets are complete score-prefixes of the
// global ranking; greedy suppression is intra-class and flows down-rank, so if
// >=100 prefix candidates survive NMS they are exactly the reference's first
// 100 picks (verified at runtime; widen then exact full fallback otherwise).
// ---------------------------------------------------------------------------

#define BATCH   16
#define NCLS    80
#define NTOT    17064          // 12800 + 3200 + 800 + 208 + 56
#define NGROUP  (NTOT / 4)     // 4266
#define POSTK   100
#define CAP     4096           // gmem candidate list capacity
#define KCAP    2048           // smem working-set capacity
#define CLSCAP  256
#define NBIN    1024
#define NTN     1024
#define T0      0.88f
#define TK1     192            // attempt-0 prefix target
#define KCAP1   512            // attempt-0 prefix cap (bump threshold above)

__device__ float         g_score[BATCH * NTOT];
__device__ unsigned char g_cls  [BATCH * NTOT];
__device__ int           g_cnt  [BATCH];          // zero-init at load
__device__ float         g_cand_s[BATCH * CAP];
__device__ int           g_cand_i[BATCH * CAP];   // anchor | (cls<<16)

struct LevelPtrs {
    const float* cls[5];
    const float* box[5];
    const float* ctr[5];
};

__constant__ int   c_off[6]    = {0, 12800, 16000, 16800, 17008, 17064};
__constant__ int   c_W[5]      = {128, 64, 32, 16, 8};
__constant__ float c_stride[5] = {8.f, 16.f, 32.f, 64.f, 128.f};

__device__ __forceinline__ float sigmoidf_(float x) {
    return 1.0f / (1.0f + expf(-x));
}
__device__ __forceinline__ float iou_(const float4 a, const float4 b) {
    float ix1 = fmaxf(a.x, b.x), iy1 = fmaxf(a.y, b.y);
    float ix2 = fminf(a.z, b.z), iy2 = fminf(a.w, b.w);
    float inter = fmaxf(ix2 - ix1, 0.f) * fmaxf(iy2 - iy1, 0.f);
    float aa = (a.z - a.x) * (a.w - a.y);
    float ab = (b.z - b.x) * (b.w - b.y);
    return inter / (aa + ab - inter + 1e-9f);
}
__device__ __forceinline__ float4 decode_box(const LevelPtrs& p, int b, int a) {
    int lvl = (a >= 12800) + (a >= 16000) + (a >= 16800) + (a >= 17008);
    int   hw     = a - c_off[lvl];
    int   HW     = c_off[lvl + 1] - c_off[lvl];
    int   W      = c_W[lvl];
    float stride = c_stride[lvl];
    const float* bp = p.box[lvl] + (size_t)b * 4 * HW + hw;
    float l  = bp[0]      * stride;
    float t  = bp[HW]     * stride;
    float r  = bp[2 * HW] * stride;
    float d  = bp[3 * HW] * stride;
    float px = (hw % W) * stride + 0.5f * stride;
    float py = (hw / W) * stride + 0.5f * stride;
    return make_float4(fminf(fmaxf(px - l, 0.f), 1023.f),
                       fminf(fmaxf(py - t, 0.f), 799.f),
                       fminf(fmaxf(px + r, 0.f), 1023.f),
                       fminf(fmaxf(py + d, 0.f), 799.f));
}

// ---------------------------------------------------------------------------
// Decode: scores + classes; push candidates >= T0. One thread per 4 anchors.
// ---------------------------------------------------------------------------
__global__ void decode_kernel(LevelPtrs p) {
    int g = blockIdx.x * blockDim.x + threadIdx.x;
    int b = blockIdx.y;
    if (g >= NGROUP) return;
    int a0 = g * 4;

    int lvl = (a0 >= 12800) + (a0 >= 16000) + (a0 >= 16800) + (a0 >= 17008);
    int hw0 = a0 - c_off[lvl];
    int HW  = c_off[lvl + 1] - c_off[lvl];
    int HW4 = HW >> 2;

    const float4* __restrict__ cp = reinterpret_cast<const float4*>(
        p.cls[lvl] + (size_t)b * NCLS * HW + hw0);
    float4 best = cp[0];
    int4   bi   = make_int4(0, 0, 0, 0);
#pragma unroll 8
    for (int c = 1; c < NCLS; c++) {
        float4 v = cp[(size_t)c * HW4];
        if (v.x > best.x) { best.x = v.x; bi.x = c; }
        if (v.y > best.y) { best.y = v.y; bi.y = c; }
        if (v.z > best.z) { best.z = v.z; bi.z = c; }
        if (v.w > best.w) { best.w = v.w; bi.w = c; }
    }

    float4 ct = *reinterpret_cast<const float4*>(p.ctr[lvl] + (size_t)b * HW + hw0);

    float4 s4;
    s4.x = sqrtf(sigmoidf_(best.x) * sigmoidf_(ct.x));
    s4.y = sqrtf(sigmoidf_(best.y) * sigmoidf_(ct.y));
    s4.z = sqrtf(sigmoidf_(best.z) * sigmoidf_(ct.z));
    s4.w = sqrtf(sigmoidf_(best.w) * sigmoidf_(ct.w));

    int gi = b * NTOT + a0;
    reinterpret_cast<float4*>(g_score)[gi >> 2] = s4;
    *reinterpret_cast<uchar4*>(&g_cls[gi]) =
        make_uchar4((unsigned char)bi.x, (unsigned char)bi.y,
                    (unsigned char)bi.z, (unsigned char)bi.w);

    float sA[4] = {s4.x, s4.y, s4.z, s4.w};
    int   cA[4] = {bi.x, bi.y, bi.z, bi.w};
#pragma unroll
    for (int j = 0; j < 4; j++) {
        if (sA[j] >= T0) {
            int pos = atomicAdd(&g_cnt[b], 1);
            if (pos < CAP) {
                g_cand_s[b * CAP + pos] = sA[j];
                g_cand_i[b * CAP + pos] = (a0 + j) | (cA[j] << 16);
            }
        }
    }
}

// ---------------------------------------------------------------------------
// NMS: one block per batch.
// ---------------------------------------------------------------------------
extern __shared__ char smemn[];

__global__ void __launch_bounds__(NTN, 1) nms_kernel(LevelPtrs p,
                                                     float* __restrict__ out) {
    float4*         wbox     = (float4*)smemn;                         // 32K
    float*          ts       = (float*)(smemn + KCAP * 16);            // 8K
    int*            tp       = (int*)((char*)ts + KCAP * 4);           // 8K
    float*          ws       = (float*)((char*)tp + KCAP * 4);         // 8K
    int*            wi       = (int*)((char*)ws + KCAP * 4);           // 8K
    unsigned char*  wc       = (unsigned char*)((char*)wi + KCAP * 4); // 2K
    unsigned char*  wkeep    = wc + KCAP;                              // 2K
    unsigned short* cls_list = (unsigned short*)(wkeep + KCAP);        // 40K
    int*            hist     = (int*)((char*)cls_list + NCLS * CLSCAP * 2); // 4K

    __shared__ int s_part[32];
    __shared__ int s_chunk[KCAP / 32 + 1];
    __shared__ int s_ccnt[NCLS];
    __shared__ int s_t, s_K, s_ovf, s_S;
    __shared__ float  s_bv[32];
    __shared__ int    s_bi[32];
    __shared__ float4 s_pbox;
    __shared__ int    s_pcls;
    __shared__ float  s_pval;

    const int b    = blockIdx.x;
    const int tid  = threadIdx.x;
    const int warp = tid >> 5;
    const int lane = tid & 31;

    const int total = g_cnt[b];
    const int C     = min(total, CAP);
    if (tid == 0) g_cnt[b] = 0;          // reset for next graph replay

    bool need_fallback = (total > CAP) || (total > KCAP);
    int  wrote = 0;
    const float binscale = (float)NBIN / (1.0f - T0);

    if (!need_fallback) {
        // ---- histogram of candidate scores over [T0, 1) -------------------
        hist[tid] = 0;
        __syncthreads();
        for (int i = tid; i < C; i += NTN) {
            float s = g_cand_s[b * CAP + i];
            int bin = min(NBIN - 1, max(0, (int)((s - T0) * binscale)));
            atomicAdd(&hist[bin], 1);
        }
        __syncthreads();
        // ---- suffix sum (warp shuffles) -----------------------------------
        {
            int val = hist[tid];
#pragma unroll
            for (int off = 1; off < 32; off <<= 1) {
                int v = __shfl_down_sync(0xffffffffu, val, off);
                if (lane + off < 32) val += v;
            }
            if (lane == 0) s_part[warp] = val;
            __syncthreads();
            if (warp == 0) {
                int pv = s_part[lane];
#pragma unroll
                for (int off = 1; off < 32; off <<= 1) {
                    int v = __shfl_down_sync(0xffffffffu, pv, off);
                    if (lane + off < 32) pv += v;
                }
                int excl = __shfl_down_sync(0xffffffffu, pv, 1);
                if (lane == 31) excl = 0;
                s_part[lane] = excl;
            }
            __syncthreads();
            hist[tid] = val + s_part[warp];  // suffix count of bins >= tid
            __syncthreads();
        }

        for (int attempt = 0; attempt < 2 && !wrote && !need_fallback; attempt++) {
            if (tid == 0) { s_t = 0; s_K = 0; s_ovf = 0; }
            __syncthreads();
            if (attempt == 0) {
                if (hist[tid] >= TK1 && (tid == NBIN - 1 || hist[tid + 1] < TK1))
                    s_t = tid;
            }
            __syncthreads();
            int t = s_t;
            if (attempt == 0 && t < NBIN - 1 && hist[t] > KCAP1) t = t + 1;

            // ---- compact prefix candidates into working set ---------------
            for (int i = tid; i < C; i += NTN) {
                float s = g_cand_s[b * CAP + i];
                int bin = min(NBIN - 1, max(0, (int)((s - T0) * binscale)));
                if (bin >= t) {
                    int pos = atomicAdd(&s_K, 1);
                    if (pos < KCAP) {
                        ts[pos] = s;
                        tp[pos] = g_cand_i[b * CAP + i];
                    }
                }
            }
            __syncthreads();
            int K = min(s_K, KCAP);

            // ---- global rank sort (score desc, anchor idx asc) ------------
            for (int i = tid; i < K; i += NTN) {
                float si  = ts[i];
                int   pki = tp[i];
                int   ai  = pki & 0xFFFF;
                int   r   = 0;
                for (int j = 0; j < K; j++) {
                    float sj = ts[j];
                    r += (sj > si) || (sj == si && (tp[j] & 0xFFFF) < ai);
                }
                ws[r]    = si;
                wi[r]    = ai;
                wc[r]    = (unsigned char)(pki >> 16);
                wbox[r]  = decode_box(p, b, ai);
                wkeep[r] = 1;
            }
            __syncthreads();

            // ---- per-class compaction (sorted order preserved) ------------
            for (int c = warp; c < NCLS; c += 32) {
                int m = 0;
                for (int base = 0; base < K; base += 32) {
                    int  i  = base + lane;
                    bool pr = (i < K) && (wc[i] == (unsigned char)c);
                    unsigned mask = __ballot_sync(0xffffffffu, pr);
                    if (pr) {
                        int pos = m + __popc(mask & ((1u << lane) - 1));
                        if (pos < CLSCAP)
                            cls_list[c * CLSCAP + pos] = (unsigned short)i;
                    }
                    m += __popc(mask);
                }
                if (lane == 0) {
                    s_ccnt[c] = m;
                    if (m > CLSCAP) atomicExch(&s_ovf, 1);
                }
            }
            __syncthreads();
            if (s_ovf) { need_fallback = true; break; }

            // ---- per-class greedy (order already sorted) ------------------
            for (int c = warp; c < NCLS; c += 32) {
                int m = s_ccnt[c];
                const unsigned short* L = cls_list + c * CLSCAP;
                for (int r = 0; r < m; r++) {
                    int ir = L[r];
                    if (wkeep[ir]) {
                        float4 pb = wbox[ir];
                        for (int j = r + 1 + lane; j < m; j += 32) {
                            int ij = L[j];
                            if (wkeep[ij] && iou_(pb, wbox[ij]) > 0.6f)
                                wkeep[ij] = 0;
                        }
                    }
                    __syncwarp();
                }
            }
            __syncthreads();

            // ---- survivor ranks via ballot + chunk prefix scan ------------
            int nchunk = (K + 31) / 32;
            for (int chunk = warp; chunk < nchunk; chunk += 32) {
                int  i  = chunk * 32 + lane;
                bool kp = (i < K) && wkeep[i];
                unsigned mask = __ballot_sync(0xffffffffu, kp);
                if (lane == 0) s_chunk[chunk] = __popc(mask);
            }
            __syncthreads();
            if (warp == 0) {
                int v0 = (lane < nchunk) ? s_chunk[lane] : 0;
                int v1 = (lane + 32 < nchunk) ? s_chunk[lane + 32] : 0;
                int i0 = v0;
#pragma unroll
                for (int off = 1; off < 32; off <<= 1) {
                    int x = __shfl_up_sync(0xffffffffu, i0, off);
                    if (lane >= off) i0 += x;
                }
                int tot0 = __shfl_sync(0xffffffffu, i0, 31);
                int i1 = v1;
#pragma unroll
                for (int off = 1; off < 32; off <<= 1) {
                    int x = __shfl_up_sync(0xffffffffu, i1, off);
                    if (lane >= off) i1 += x;
                }
                if (lane < nchunk)      s_chunk[lane]      = i0 - v0;
                if (lane + 32 < nchunk) s_chunk[lane + 32] = tot0 + i1 - v1;
                if (lane == 31) s_S = tot0 + i1;
            }
            __syncthreads();
            int S = s_S;

            if (S >= POSTK) {
                for (int chunk = warp; chunk < nchunk; chunk += 32) {
                    int  i  = chunk * 32 + lane;
                    bool kp = (i < K) && wkeep[i];
                    unsigned mask = __ballot_sync(0xffffffffu, kp);
                    if (kp) {
                        int r = s_chunk[chunk] + __popc(mask & ((1u << lane) - 1));
                        if (r < POSTK) {
                            float4 bb  = wbox[i];
                            float* det = out + ((size_t)b * POSTK + r) * 5;
                            det[0] = bb.x; det[1] = bb.y;
                            det[2] = bb.z; det[3] = bb.w;
                            det[4] = ws[i];
                            out[(size_t)BATCH * POSTK * 5 + b * POSTK + r] =
                                (float)wc[i];
                        }
                    }
                }
                wrote = 1;
            }
            __syncthreads();
        }
        if (!wrote) need_fallback = true;  // <100 survivors even with all >=T0
    }

    if (wrote) return;

    // ---- fallback: exact block-serial greedy over all anchors -------------
    // (statistically unreachable; g_score is replay-rewritten scratch)
    {
        float* gsm = g_score + b * NTOT;
        int written = 0;
        for (int k = 0; k < POSTK; k++) {
            float bv = -1e30f; int bix = 0x7fffffff;
            for (int i = tid; i < NTOT; i += NTN) {
                float s = gsm[i];
                if (s > bv || (s == bv && i < bix)) { bv = s; bix = i; }
            }
#pragma unroll
            for (int off = 16; off; off >>= 1) {
                float ov = __shfl_down_sync(0xffffffffu, bv, off);
                int   oi = __shfl_down_sync(0xffffffffu, bix, off);
                if (ov > bv || (ov == bv && oi < bix)) { bv = ov; bix = oi; }
            }
            if (lane == 0) { s_bv[warp] = bv; s_bi[warp] = bix; }
            __syncthreads();
            if (tid == 0) {
                float fv = -1e30f; int fi = 0x7fffffff;
                for (int w2 = 0; w2 < 32; w2++) {
                    float cv = s_bv[w2]; int ci = s_bi[w2];
                    if (cv > fv || (cv == fv && ci < fi)) { fv = cv; fi = ci; }
                }
                s_pval = fv;
                if (fv > -1e29f) {
                    float4 pb = decode_box(p, b, fi);
                    s_pbox = pb;
                    s_pcls = g_cls[b * NTOT + fi];
                    float* det = out + ((size_t)b * POSTK + k) * 5;
                    det[0] = pb.x; det[1] = pb.y; det[2] = pb.z; det[3] = pb.w;
                    det[4] = fv;
                    out[(size_t)BATCH * POSTK * 5 + b * POSTK + k] =
                        (float)s_pcls;
                    gsm[fi] = -1e30f;
                }
            }
            __syncthreads();
            if (s_pval <= -1e29f) break;
            written++;
            float4 pb = s_pbox;
            int    pc = s_pcls;
            for (int i = tid; i < NTOT; i += NTN) {
                float s = gsm[i];
                if (s > -1e29f && g_cls[b * NTOT + i] == pc) {
                    if (iou_(pb, decode_box(p, b, i)) > 0.6f) gsm[i] = -1e30f;
                }
            }
            __syncthreads();
        }
        for (int k = written + tid; k < POSTK; k += NTN) {
            float* det = out + ((size_t)b * POSTK + k) * 5;
            det[0] = 0.f; det[1] = 0.f; det[2] = 0.f; det[3] = 0.f; det[4] = -1.f;
            out[(size_t)BATCH * POSTK * 5 + b * POSTK + k] = -1.f;
        }
    }
}

// ---------------------------------------------------------------------------
extern "C" void kernel_launch(void* const* d_in, const int* in_sizes, int n_in,
                              void* d_out, int out_size) {
    (void)n_in; (void)out_size;

    LevelPtrs p;
    if (in_sizes[1] == 819200) {
        for (int i = 0; i < 5; i++) {          // interleaved (cls,box,ctr)/level
            p.cls[i] = (const float*)d_in[3 * i + 0];
            p.box[i] = (const float*)d_in[3 * i + 1];
            p.ctr[i] = (const float*)d_in[3 * i + 2];
        }
    } else {
        for (int i = 0; i < 5; i++) {          // planar cls x5, box x5, ctr x5
            p.cls[i] = (const float*)d_in[i];
            p.box[i] = (const float*)d_in[5 + i];
            p.ctr[i] = (const float*)d_in[10 + i];
        }
    }

    const int smem_bytes = KCAP * 16 + KCAP * 4 * 4 + KCAP * 2
                         + NCLS * CLSCAP * 2 + NBIN * 4;   // 114,688 B
    cudaFuncSetAttribute(nms_kernel,
                         cudaFuncAttributeMaxDynamicSharedMemorySize, smem_bytes);

    dim3 dgrid((NGROUP + 255) / 256, BATCH);
    decode_kernel<<<dgrid, 256>>>(p);

    nms_kernel<<<BATCH, NTN, smem_bytes>>>(p, (float*)d_out);
}